// round 4
// baseline (speedup 1.0000x reference)
#include <cuda_runtime.h>

#define Nst 512
#define Tc  128
#define Cc  512
#define Lt  65536
#define TN  (Tc * Nst)

// Scratch (static device arrays; no allocation at runtime)
__device__ float g_pow[15][Nst * Nst];   // g_pow[e-1] = Ab^(2^e), e=1..15
__device__ float g_G[Tc * Nst];          // G[m] = A^m b
__device__ float g_Grev[Tc * Nst];       // Grev[i] = G[T-1-i]
__device__ float g_Gmat[Tc * TN];        // Toeplitz-expanded conv kernel (33.5 MB)
__device__ float g_R0[Cc * Nst];
__device__ float g_R1[Cc * Nst];

__device__ __forceinline__ long rowOff(int r, long base, int brk, long bs, long rs) {
    if (brk == 1) return base + (long)r * bs;
    return base + (long)(r / brk) * bs + (long)(r % brk) * rs;
}

// Generic guarded SGEMM: C[M x Nn] = A[M x K] @ op(B) (+ beta*C)
// A rows addressed via (base, brk, blockStride, rowStride) to support
// strided/blocked row sets living inside the output tensor.
__global__ void sgemm_k(const float* __restrict__ A, const float* __restrict__ B,
                        float* __restrict__ C,
                        int M, int Nn, int K,
                        long aBase, int aBRK, long aBS, long aRS,
                        long bLd, int bTrans,
                        long cBase, int cBRK, long cBS, long cRS,
                        float beta)
{
    __shared__ float As[8][132];
    __shared__ float Bs[8][132];
    int tid = threadIdx.x;
    int bm = blockIdx.y * 128;
    int bn = blockIdx.x * 128;
    int tr = (tid >> 4) << 3;
    int tc = (tid & 15) << 3;
    float acc[8][8];
#pragma unroll
    for (int i = 0; i < 8; i++)
#pragma unroll
        for (int j = 0; j < 8; j++) acc[i][j] = 0.f;

    for (int k0 = 0; k0 < K; k0 += 8) {
#pragma unroll
        for (int i = 0; i < 4; i++) {
            int idx = tid + i * 256;
            int k = idx & 7, m = idx >> 3;
            int gr = bm + m, gk = k0 + k;
            float v = 0.f;
            if (gr < M && gk < K) v = A[rowOff(gr, aBase, aBRK, aBS, aRS) + gk];
            As[k][m] = v;
        }
#pragma unroll
        for (int i = 0; i < 4; i++) {
            int idx = tid + i * 256;
            int k, n;
            if (bTrans) { k = idx & 7; n = idx >> 3; }
            else        { n = idx & 127; k = idx >> 7; }
            int gn = bn + n, gk = k0 + k;
            float v = 0.f;
            if (gn < Nn && gk < K)
                v = bTrans ? B[(long)gn * bLd + gk] : B[(long)gk * bLd + gn];
            Bs[k][n] = v;
        }
        __syncthreads();
#pragma unroll
        for (int k = 0; k < 8; k++) {
            float a[8], b[8];
#pragma unroll
            for (int i = 0; i < 8; i++) a[i] = As[k][tr + i];
#pragma unroll
            for (int j = 0; j < 8; j++) b[j] = Bs[k][tc + j];
#pragma unroll
            for (int i = 0; i < 8; i++)
#pragma unroll
                for (int j = 0; j < 8; j++) acc[i][j] += a[i] * b[j];
        }
        __syncthreads();
    }

#pragma unroll
    for (int i = 0; i < 8; i++) {
        int gr = bm + tr + i;
        if (gr < M) {
            long ro = rowOff(gr, cBase, cBRK, cBS, cRS);
#pragma unroll
            for (int j = 0; j < 8; j++) {
                int gn = bn + tc + j;
                if (gn < Nn) {
                    float v = acc[i][j];
                    if (beta != 0.f) v += beta * C[ro + gn];
                    C[ro + gn] = v;
                }
            }
        }
    }
}

__global__ void rev_k() {
    int idx = blockIdx.x * blockDim.x + threadIdx.x;
    if (idx < Tc * Nst) {
        int i = idx / Nst, n = idx % Nst;
        g_Grev[idx] = g_G[(Tc - 1 - i) * Nst + n];
    }
}

__global__ void gmat_k() {
    int idx = blockIdx.x * blockDim.x + threadIdx.x;
    if (idx < Tc * TN) {
        int i = idx / TN;
        int rem = idx - i * TN;
        int j = rem / Nst;
        int n = rem - j * Nst;
        g_Gmat[idx] = (j >= i) ? g_G[(j - i) * Nst + n] : 0.f;
    }
}

static void gemm(const float* A, const float* B, float* C, int M, int Nn, int K,
                 long aBase, int aBRK, long aBS, long aRS,
                 long bLd, int bTrans,
                 long cBase, int cBRK, long cBS, long cRS, float beta)
{
    dim3 grid((Nn + 127) / 128, (M + 127) / 128);
    sgemm_k<<<grid, 256>>>(A, B, C, M, Nn, K, aBase, aBRK, aBS, aRS,
                           bLd, bTrans, cBase, cBRK, cBS, cRS, beta);
}

extern "C" void kernel_launch(void* const* d_in, const int* in_sizes, int n_in,
                              void* d_out, int out_size)
{
    const float* u  = (const float*)d_in[0];   // (L,)
    const float* Ab = (const float*)d_in[1];   // (N,N)
    const float* Bb = (const float*)d_in[2];   // (N,1) -> b contiguous
    const float* x0 = (const float*)d_in[3];   // (N,)
    float* out = (float*)d_out;                // (L,N) row-major

    float *pw, *G, *Grev, *Gmat, *R0, *R1;
    cudaGetSymbolAddress((void**)&pw,   g_pow);
    cudaGetSymbolAddress((void**)&G,    g_G);
    cudaGetSymbolAddress((void**)&Grev, g_Grev);
    cudaGetSymbolAddress((void**)&Gmat, g_Gmat);
    cudaGetSymbolAddress((void**)&R0,   g_R0);
    cudaGetSymbolAddress((void**)&R1,   g_R1);

    auto P = [&](int e) { return pw + (long)(e - 1) * (Nst * Nst); }; // Ab^(2^e)

    // ---- 1. Power chain: P(e) = P(e-1)^2, P(0) := Ab ----
    for (int e = 1; e <= 15; e++) {
        const float* X = (e == 1) ? Ab : P(e - 1);
        gemm(X, X, P(e), Nst, Nst, Nst,
             0, 1, Nst, 0,   Nst, 0,   0, 1, Nst, 0, 0.f);
    }

    // ---- 2. Conv kernel G[m] = A^m b via doubling ----
    cudaMemcpyAsync(G, Bb, Nst * sizeof(float), cudaMemcpyDeviceToDevice);
    for (int t = 0; t <= 6; t++) {
        int s = 1 << t;
        const float* Ps = (t == 0) ? Ab : P(t);
        // G[s..2s) = G[0..s) @ (A^s)^T
        gemm(G, Ps, G + (long)s * Nst, s, Nst, Nst,
             0, 1, Nst, 0,   Nst, 1,   0, 1, Nst, 0, 0.f);
    }
    rev_k<<<(Tc * Nst + 255) / 256, 256>>>();

    // ---- 3. Driving terms: d[0]=x0, d[c]=Grev-projected chunk inputs ----
    cudaMemcpyAsync(R0, x0, Nst * sizeof(float), cudaMemcpyDeviceToDevice);
    // rows 1..C-1: V[c] = u_chunk[c-1] @ Grev   (M=C-1, K=T)
    gemm(u, Grev, R0 + Nst, Cc - 1, Nst, Tc,
         0, 1, Tc, 0,   Nst, 0,   0, 1, Nst, 0, 0.f);

    // ---- 4. Log-doubling GEMM scan for chunk states: 9 levels ----
    float* cur = R0; float* nxt = R1;
    for (int k = 0; k < 9; k++) {
        int h = 1 << k;
        cudaMemcpyAsync(nxt, cur, (size_t)Cc * Nst * sizeof(float),
                        cudaMemcpyDeviceToDevice);
        // nxt[h:] += cur[:C-h] @ (A^(128*2^k))^T ; A^(2^(7+k)) = P(7+k)
        gemm(cur, P(7 + k), nxt + (long)h * Nst, Cc - h, Nst, Nst,
             0, 1, Nst, 0,   Nst, 1,   0, 1, Nst, 0, 1.f);
        float* tmp = cur; cur = nxt; nxt = tmp;
    }
    float* St = cur;   // St[c] = s_c (state entering chunk c)

    // ---- 5. Part A stage 1: out rows j = 0..7 (chained by Ab^T), strided into d_out
    for (int q0 = 1; q0 <= 8; q0++) {
        const float* Ain = (q0 == 1) ? St : out;
        long aBase = (q0 == 1) ? 0 : (long)(q0 - 2) * Nst;
        long aBS   = (q0 == 1) ? (long)Nst : (long)TN;
        gemm(Ain, Ab, out, Cc, Nst, Nst,
             aBase, 1, aBS, 0,   Nst, 1,
             (long)(q0 - 1) * Nst, 1, TN, 0, 0.f);
    }
    // ---- 6. Part A stage 2: 8-row blocks chained by (A^8)^T, j = 8..127
    for (int q1 = 1; q1 <= 15; q1++) {
        gemm(out, P(3), out, Cc * 8, Nst, Nst,
             (long)(q1 - 1) * 8 * Nst, 8, (long)TN, (long)Nst,
             Nst, 1,
             (long)q1 * 8 * Nst, 8, (long)TN, (long)Nst, 0.f);
    }

    // ---- 7. Part B: within-chunk causal conv as one GEMM, accumulated into out
    gmat_k<<<(Tc * TN + 255) / 256, 256>>>();
    gemm(u, Gmat, out, Cc, TN, Tc,
         0, 1, Tc, 0,   (long)TN, 0,   0, 1, (long)TN, 0, 1.f);

    (void)in_sizes; (void)n_in; (void)out_size;
}

// round 7
// speedup vs baseline: 2.2198x; 2.2198x over previous
#include <cuda_runtime.h>

#define Nst 512
#define Tc  128
#define Cc  512
#define TN  (Tc * Nst)
#define NN  ((long)Nst * Nst)

typedef unsigned long long ull;

// Scratch (static device arrays; no runtime allocation)
// g_pw slots: 0..7 = A^1..A^8 ; 8=A^16, 9=A^32, 10=A^64 ; 11..19 = A^(128*2^k), k=0..8
__device__ float g_pw[20][Nst * Nst];
__device__ float g_G[Tc * Nst];       // G[m] = A^m b
__device__ float g_Grev[Tc * Nst];
__device__ float g_Gmat[Tc * TN];     // Toeplitz-expanded conv kernel
__device__ float g_R0[Cc * Nst];
__device__ float g_R1[Cc * Nst];

// ---- packed fp32x2 helpers (FFMA2 is only reachable via PTX fma.rn.f32x2) ----
__device__ __forceinline__ ull dup2(float x) {
    unsigned xi = __float_as_uint(x);
    ull d; asm("mov.b64 %0, {%1, %1};" : "=l"(d) : "r"(xi));
    return d;
}
__device__ __forceinline__ void fma2(ull &c, ull a, ull b) {
    asm("fma.rn.f32x2 %0, %1, %2, %0;" : "+l"(c) : "l"(a), "l"(b));
}
__device__ __forceinline__ float2 upk(ull c) {
    unsigned lo, hi;
    asm("mov.b64 {%0, %1}, %2;" : "=r"(lo), "=r"(hi) : "l"(c));
    float2 f; f.x = __uint_as_float(lo); f.y = __uint_as_float(hi);
    return f;
}

__device__ __forceinline__ long rowOff(int r, long base, int brk, long bs, long rs) {
    if (brk == 1) return base + (long)r * bs;
    return base + (long)(r / brk) * bs + (long)(r % brk) * rs;
}

// ============================================================================
// SGEMM: C[M x Nn] = A @ op(B) (+ D), tile 64x128, BK=16, 256 threads,
// 4x8 per-thread via f32x2, double-buffered smem, z-batched.
// Requirements: K % 16 == 0, Nn % 128 == 0 (true for all call sites).
// ============================================================================
__global__ void __launch_bounds__(256, 2)
gemm_k(const float* __restrict__ A, const float* __restrict__ B,
       float* __restrict__ C, const float* __restrict__ Dp,
       int M, int K,
       long aBase, int aBRK, long aBS, long aRS, long aZS,
       long bLd, int bTrans, long bZS,
       long cBase, int cBRK, long cBS, long cRS, long cZS,
       long dBase)
{
    __shared__ __align__(16) float As[2][16][68];
    __shared__ __align__(16) float Bs[2][16][132];

    int tid = threadIdx.x;
    int bm = blockIdx.y * 64;
    int bn = blockIdx.x * 128;
    int z  = blockIdx.z;
    A += (long)z * aZS; B += (long)z * bZS; C += (long)z * cZS;

    // A loader: one row per thread, 1 float4 along k
    int am   = tid >> 2;
    int arow = bm + am;
    int ak   = (tid & 3) * 4;
    bool aval = arow < M;
    const float* ap = A + rowOff(aval ? arow : 0, aBase, aBRK, aBS, aRS) + ak;

    // B loader
    const float* bp;
    int bn0 = 0, bkr = 0, bnr = 0, bkq = 0;
    if (bTrans) {
        bnr = tid >> 1;
        bkq = (tid & 1) * 8;
        bp  = B + (long)(bn + bnr) * bLd + bkq;
    } else {
        bkr = tid >> 4;
        bn0 = (tid & 15) * 4;
        bp  = B + (long)bkr * bLd + bn + bn0;
    }

    auto ldA = [&](float4 &a4) {
        a4 = aval ? *(const float4*)ap : make_float4(0.f, 0.f, 0.f, 0.f);
        ap += 16;
    };
    auto ldB = [&](float4 &b0, float4 &b1) {
        if (bTrans) { b0 = *(const float4*)bp; b1 = *(const float4*)(bp + 4); bp += 16; }
        else        { b0 = *(const float4*)bp; b1 = *(const float4*)(bp + 64); bp += (long)16 * bLd; }
    };
    auto sts = [&](int b, float4 a4, float4 b0, float4 b1) {
        As[b][ak + 0][am] = a4.x; As[b][ak + 1][am] = a4.y;
        As[b][ak + 2][am] = a4.z; As[b][ak + 3][am] = a4.w;
        if (bTrans) {
            Bs[b][bkq + 0][bnr] = b0.x; Bs[b][bkq + 1][bnr] = b0.y;
            Bs[b][bkq + 2][bnr] = b0.z; Bs[b][bkq + 3][bnr] = b0.w;
            Bs[b][bkq + 4][bnr] = b1.x; Bs[b][bkq + 5][bnr] = b1.y;
            Bs[b][bkq + 6][bnr] = b1.z; Bs[b][bkq + 7][bnr] = b1.w;
        } else {
            *(float4*)&Bs[b][bkr][bn0]      = b0;
            *(float4*)&Bs[b][bkr][bn0 + 64] = b1;
        }
    };

    int ty = tid >> 4, tx = tid & 15;
    int tr = ty * 4, tc = tx * 8;

    ull acc[4][4];
#pragma unroll
    for (int i = 0; i < 4; i++)
#pragma unroll
        for (int p = 0; p < 4; p++) acc[i][p] = 0ULL;

    int nt = K >> 4;
    float4 av, bv0, bv1;
    ldA(av); ldB(bv0, bv1);
    sts(0, av, bv0, bv1);
    __syncthreads();

    for (int t = 0; t < nt; t++) {
        int buf = t & 1;
        bool more = (t + 1) < nt;
        if (more) { ldA(av); ldB(bv0, bv1); }
#pragma unroll
        for (int kk = 0; kk < 16; kk++) {
            float4 a4 = *(const float4*)&As[buf][kk][tr];
            ulonglong2 q0 = *(const ulonglong2*)&Bs[buf][kk][tc];
            ulonglong2 q1 = *(const ulonglong2*)&Bs[buf][kk][tc + 4];
            ull ad0 = dup2(a4.x), ad1 = dup2(a4.y), ad2 = dup2(a4.z), ad3 = dup2(a4.w);
            ull bd[4] = {q0.x, q0.y, q1.x, q1.y};
#pragma unroll
            for (int p = 0; p < 4; p++) {
                fma2(acc[0][p], ad0, bd[p]);
                fma2(acc[1][p], ad1, bd[p]);
                fma2(acc[2][p], ad2, bd[p]);
                fma2(acc[3][p], ad3, bd[p]);
            }
        }
        if (more) sts(buf ^ 1, av, bv0, bv1);
        __syncthreads();
    }

#pragma unroll
    for (int i = 0; i < 4; i++) {
        int gr = bm + tr + i;
        if (gr < M) {
            long ro  = rowOff(gr, cBase, cBRK, cBS, cRS);
            long dro = Dp ? rowOff(gr, dBase, cBRK, cBS, cRS) : 0;
#pragma unroll
            for (int p = 0; p < 4; p++) {
                float2 v = upk(acc[i][p]);
                int n = bn + tc + 2 * p;
                if (Dp) { v.x += Dp[dro + n]; v.y += Dp[dro + n + 1]; }
                *(float2*)&C[ro + n] = v;
            }
        }
    }
}

// G[j] = A^j b for j=1..8 (powers already built; fully parallel matvecs)
__global__ void gvec_k(const float* __restrict__ b) {
    __shared__ float bs[Nst];
    int t = threadIdx.x;
    for (int i = t; i < Nst; i += 256) bs[i] = b[i];
    __syncthreads();
    int idx = blockIdx.x * 256 + t;
    int j = idx >> 9;            // 0..7 -> power A^(j+1)
    int n = idx & 511;
    const float* row = g_pw[j] + (long)n * Nst;
    float s = 0.f;
#pragma unroll 8
    for (int k = 0; k < Nst; k++) s += row[k] * bs[k];
    g_G[(long)(j + 1) * Nst + n] = s;
}

__global__ void rev_k() {
    int idx = blockIdx.x * 256 + threadIdx.x;   // float4 index, total Tc*Nst/4
    int n4 = idx & 127;
    int i  = idx >> 7;
    *(float4*)&g_Grev[(long)i * Nst + n4 * 4] =
        *(const float4*)&g_G[(long)(Tc - 1 - i) * Nst + n4 * 4];
}

__global__ void gmat_k() {
    long idx = (long)blockIdx.x * 256 + threadIdx.x;  // float4 index
    int n4 = (int)(idx & 127);
    long r = idx >> 7;
    int j = (int)(r & (Tc - 1));
    int i = (int)(r >> 7);
    float4 v = make_float4(0.f, 0.f, 0.f, 0.f);
    if (j >= i) v = *(const float4*)&g_G[(long)(j - i) * Nst + n4 * 4];
    *(float4*)&g_Gmat[(long)i * TN + (long)j * Nst + n4 * 4] = v;
}

static void gemm(const float* A, const float* B, float* C, const float* Dp,
                 int M, int Nn, int K,
                 long aBase, int aBRK, long aBS, long aRS, long aZS,
                 long bLd, int bTrans, long bZS,
                 long cBase, int cBRK, long cBS, long cRS, long cZS,
                 long dBase, int nz)
{
    dim3 grid(Nn / 128, (M + 63) / 64, nz);
    gemm_k<<<grid, 256>>>(A, B, C, Dp, M, K,
                          aBase, aBRK, aBS, aRS, aZS,
                          bLd, bTrans, bZS,
                          cBase, cBRK, cBS, cRS, cZS, dBase);
}

extern "C" void kernel_launch(void* const* d_in, const int* in_sizes, int n_in,
                              void* d_out, int out_size)
{
    const float* u  = (const float*)d_in[0];   // (L,)
    const float* Ab = (const float*)d_in[1];   // (N,N)
    const float* Bb = (const float*)d_in[2];   // (N,1)
    const float* x0 = (const float*)d_in[3];   // (N,)
    float* out = (float*)d_out;                // (L,N)

    float *pw, *G, *Grev, *Gmat, *R0, *R1;
    cudaGetSymbolAddress((void**)&pw,   g_pw);
    cudaGetSymbolAddress((void**)&G,    g_G);
    cudaGetSymbolAddress((void**)&Grev, g_Grev);
    cudaGetSymbolAddress((void**)&Gmat, g_Gmat);
    cudaGetSymbolAddress((void**)&R0,   g_R0);
    cudaGetSymbolAddress((void**)&R1,   g_R1);

    auto PW = [&](int s) { return pw + (long)s * NN; };

    // ---- Powers: A^1..A^8 in 3 launches (z-batched), then 12 serial squarings
    cudaMemcpyAsync(PW(0), Ab, NN * sizeof(float), cudaMemcpyDeviceToDevice);
    // A^2 = A @ A
    gemm(PW(0), PW(0), PW(1), nullptr, Nst, Nst, Nst,
         0, 1, Nst, 0, 0,   Nst, 0, 0,   0, 1, Nst, 0, 0,  0, 1);
    // [A^3, A^4] = [A^1, A^2] @ A^2
    gemm(PW(0), PW(1), PW(2), nullptr, Nst, Nst, Nst,
         0, 1, Nst, 0, NN,  Nst, 0, 0,   0, 1, Nst, 0, NN, 0, 2);
    // [A^5..A^8] = [A^1..A^4] @ A^4
    gemm(PW(0), PW(3), PW(4), nullptr, Nst, Nst, Nst,
         0, 1, Nst, 0, NN,  Nst, 0, 0,   0, 1, Nst, 0, NN, 0, 4);
    // A^16, A^32, A^64, A^128, ..., A^32768
    for (int s = 8; s <= 19; s++) {
        const float* X = (s == 8) ? PW(7) : PW(s - 1);
        gemm(X, X, PW(s), nullptr, Nst, Nst, Nst,
             0, 1, Nst, 0, 0,  Nst, 0, 0,  0, 1, Nst, 0, 0, 0, 1);
    }

    // ---- Conv kernel G[0..127]: row 0 = b; rows 1..8 parallel matvecs; doublings
    cudaMemcpyAsync(G, Bb, Nst * sizeof(float), cudaMemcpyDeviceToDevice);
    gvec_k<<<16, 256>>>(Bb);
    for (int t = 3; t <= 6; t++) {          // s = 8,16,32,64 ; powers PW(7..10)
        int s = 1 << t;
        gemm(G, PW(4 + t), G + (long)s * Nst, nullptr, s, Nst, Nst,
             0, 1, Nst, 0, 0,  Nst, 1, 0,  0, 1, Nst, 0, 0, 0, 1);
    }
    rev_k<<<(Tc * Nst / 4) / 256, 256>>>();

    // ---- Driving terms d[c]
    cudaMemcpyAsync(R0, x0, Nst * sizeof(float), cudaMemcpyDeviceToDevice);
    gemm(u, Grev, R0 + Nst, nullptr, Cc - 1, Nst, Tc,
         0, 1, Tc, 0, 0,  Nst, 0, 0,  0, 1, Nst, 0, 0, 0, 1);

    // ---- Log-doubling scan over chunk states (9 levels, copy only h rows)
    float* cur = R0; float* nxt = R1;
    for (int k = 0; k < 9; k++) {
        int h = 1 << k;
        cudaMemcpyAsync(nxt, cur, (size_t)h * Nst * sizeof(float),
                        cudaMemcpyDeviceToDevice);
        // nxt[h:] = cur[:C-h] @ (A^(128*2^k))^T + cur[h:]
        gemm(cur, PW(11 + k), nxt + (long)h * Nst, cur, Cc - h, Nst, Nst,
             0, 1, Nst, 0, 0,  Nst, 1, 0,  0, 1, Nst, 0, 0,
             (long)h * Nst, 1);
        float* tmp = cur; cur = nxt; nxt = tmp;
    }
    float* St = cur;   // St[c] = state entering chunk c

    // ---- Part A stage 1: rows j=0..7 of every chunk in ONE batched GEMM (z=8)
    // out[c*T + j] = St[c] @ (A^(j+1))^T
    gemm(St, PW(0), out, nullptr, Cc, Nst, Nst,
         0, 1, Nst, 0, 0,          // A: same for all z
         Nst, 1, NN,               // B: A^(z+1), transposed
         0, 1, (long)TN, 0, (long)Nst,  // C: chunk stride TN; z shifts row j
         0, 8);

    // ---- Part A stage 2: log-doubling over row blocks (4 steps, huge M)
    // rows [R, 2R) = rows [0, R) @ (A^R)^T ; R = 8,16,32,64
    const int pwIdx[4] = {7, 8, 9, 10};     // A^8, A^16, A^32, A^64
    for (int s = 0; s < 4; s++) {
        int R = 8 << s;
        gemm(out, PW(pwIdx[s]), out, nullptr, Cc * R, Nst, Nst,
             0, R, (long)TN, (long)Nst, 0,
             Nst, 1, 0,
             (long)R * Nst, R, (long)TN, (long)Nst, 0,
             0, 1);
    }

    // ---- Part B: within-chunk causal conv, accumulated into out
    gmat_k<<<(long)Tc * TN / 4 / 256, 256>>>();
    gemm(u, Gmat, out, out, Cc, TN, Tc,
         0, 1, Tc, 0, 0,  (long)TN, 0, 0,  0, 1, (long)TN, 0, 0,
         0, 1);

    (void)in_sizes; (void)n_in; (void)out_size;
}

// round 10
// speedup vs baseline: 2.2236x; 1.0017x over previous
#include <cuda_runtime.h>

#define Nst 512
#define Tc  128
#define Cc  512
#define TN  (Tc * Nst)
#define NN  ((long)Nst * Nst)

typedef unsigned long long ull;

// Scratch (static device arrays; no runtime allocation)
// g_pw slots: 0..7 = A^1..A^8 ; 8=A^16, 9=A^32, 10=A^64 ; 11..19 = A^(128*2^k), k=0..8
__device__ float g_pw[20][Nst * Nst];
__device__ float g_G[Tc * Nst];       // G[m] = A^m b
__device__ float g_Grev[Tc * Nst];
__device__ float g_Gmat[Tc * TN];     // Toeplitz-expanded conv kernel
__device__ float g_R0[Cc * Nst];
__device__ float g_R1[Cc * Nst];

// ---- packed fp32x2 helpers (FFMA2 is only reachable via PTX fma.rn.f32x2) ----
__device__ __forceinline__ ull dup2(float x) {
    unsigned xi = __float_as_uint(x);
    ull d; asm("mov.b64 %0, {%1, %1};" : "=l"(d) : "r"(xi));
    return d;
}
__device__ __forceinline__ void fma2(ull &c, ull a, ull b) {
    asm("fma.rn.f32x2 %0, %1, %2, %0;" : "+l"(c) : "l"(a), "l"(b));
}
__device__ __forceinline__ float2 upk(ull c) {
    unsigned lo, hi;
    asm("mov.b64 {%0, %1}, %2;" : "=r"(lo), "=r"(hi) : "l"(c));
    float2 f; f.x = __uint_as_float(lo); f.y = __uint_as_float(hi);
    return f;
}

__device__ __forceinline__ long rowOff(int r, long base, int brk, long bs, long rs) {
    if (brk == 1) return base + (long)r * bs;
    return base + (long)(r / brk) * bs + (long)(r % brk) * rs;
}

// ============================================================================
// SGEMM: C[M x Nn] = A @ op(B) (+ D), tile 64x128, BK=16, 256 threads,
// 4x8 per-thread via f32x2, double-buffered smem, z-batched.
// Requirements: K % 16 == 0, Nn % 128 == 0 (true for all call sites).
// ============================================================================
__global__ void __launch_bounds__(256, 2)
gemm_k(const float* __restrict__ A, const float* __restrict__ B,
       float* __restrict__ C, const float* __restrict__ Dp,
       int M, int K,
       long aBase, int aBRK, long aBS, long aRS, long aZS,
       long bLd, int bTrans, long bZS,
       long cBase, int cBRK, long cBS, long cRS, long cZS,
       long dBase)
{
    __shared__ __align__(16) float As[2][16][68];
    __shared__ __align__(16) float Bs[2][16][132];

    int tid = threadIdx.x;
    int bm = blockIdx.y * 64;
    int bn = blockIdx.x * 128;
    int z  = blockIdx.z;
    A += (long)z * aZS; B += (long)z * bZS; C += (long)z * cZS;

    // A loader: one row per thread, 1 float4 along k
    int am   = tid >> 2;
    int arow = bm + am;
    int ak   = (tid & 3) * 4;
    bool aval = arow < M;
    const float* ap = A + rowOff(aval ? arow : 0, aBase, aBRK, aBS, aRS) + ak;

    // B loader
    const float* bp;
    int bn0 = 0, bkr = 0, bnr = 0, bkq = 0;
    if (bTrans) {
        bnr = tid >> 1;
        bkq = (tid & 1) * 8;
        bp  = B + (long)(bn + bnr) * bLd + bkq;
    } else {
        bkr = tid >> 4;
        bn0 = (tid & 15) * 4;
        bp  = B + (long)bkr * bLd + bn + bn0;
    }

    auto ldA = [&](float4 &a4) {
        a4 = aval ? *(const float4*)ap : make_float4(0.f, 0.f, 0.f, 0.f);
        ap += 16;
    };
    auto ldB = [&](float4 &b0, float4 &b1) {
        if (bTrans) { b0 = *(const float4*)bp; b1 = *(const float4*)(bp + 4); bp += 16; }
        else        { b0 = *(const float4*)bp; b1 = *(const float4*)(bp + 64); bp += (long)16 * bLd; }
    };
    auto sts = [&](int b, float4 a4, float4 b0, float4 b1) {
        As[b][ak + 0][am] = a4.x; As[b][ak + 1][am] = a4.y;
        As[b][ak + 2][am] = a4.z; As[b][ak + 3][am] = a4.w;
        if (bTrans) {
            Bs[b][bkq + 0][bnr] = b0.x; Bs[b][bkq + 1][bnr] = b0.y;
            Bs[b][bkq + 2][bnr] = b0.z; Bs[b][bkq + 3][bnr] = b0.w;
            Bs[b][bkq + 4][bnr] = b1.x; Bs[b][bkq + 5][bnr] = b1.y;
            Bs[b][bkq + 6][bnr] = b1.z; Bs[b][bkq + 7][bnr] = b1.w;
        } else {
            *(float4*)&Bs[b][bkr][bn0]      = b0;
            *(float4*)&Bs[b][bkr][bn0 + 64] = b1;
        }
    };

    int ty = tid >> 4, tx = tid & 15;
    int tr = ty * 4, tc = tx * 8;

    ull acc[4][4];
#pragma unroll
    for (int i = 0; i < 4; i++)
#pragma unroll
        for (int p = 0; p < 4; p++) acc[i][p] = 0ULL;

    int nt = K >> 4;
    float4 av, bv0, bv1;
    ldA(av); ldB(bv0, bv1);
    sts(0, av, bv0, bv1);
    __syncthreads();

    for (int t = 0; t < nt; t++) {
        int buf = t & 1;
        bool more = (t + 1) < nt;
        if (more) { ldA(av); ldB(bv0, bv1); }
#pragma unroll
        for (int kk = 0; kk < 16; kk++) {
            float4 a4 = *(const float4*)&As[buf][kk][tr];
            ulonglong2 q0 = *(const ulonglong2*)&Bs[buf][kk][tc];
            ulonglong2 q1 = *(const ulonglong2*)&Bs[buf][kk][tc + 4];
            ull ad0 = dup2(a4.x), ad1 = dup2(a4.y), ad2 = dup2(a4.z), ad3 = dup2(a4.w);
            ull bd[4] = {q0.x, q0.y, q1.x, q1.y};
#pragma unroll
            for (int p = 0; p < 4; p++) {
                fma2(acc[0][p], ad0, bd[p]);
                fma2(acc[1][p], ad1, bd[p]);
                fma2(acc[2][p], ad2, bd[p]);
                fma2(acc[3][p], ad3, bd[p]);
            }
        }
        if (more) sts(buf ^ 1, av, bv0, bv1);
        __syncthreads();
    }

#pragma unroll
    for (int i = 0; i < 4; i++) {
        int gr = bm + tr + i;
        if (gr < M) {
            long ro  = rowOff(gr, cBase, cBRK, cBS, cRS);
            long dro = Dp ? rowOff(gr, dBase, cBRK, cBS, cRS) : 0;
#pragma unroll
            for (int p = 0; p < 4; p++) {
                float2 v = upk(acc[i][p]);
                int n = bn + tc + 2 * p;
                if (Dp) { v.x += Dp[dro + n]; v.y += Dp[dro + n + 1]; }
                *(float2*)&C[ro + n] = v;
            }
        }
    }
}

// G[j] = A^j b for j=1..8 (powers already built; fully parallel matvecs)
__global__ void gvec_k(const float* __restrict__ b) {
    __shared__ float bs[Nst];
    int t = threadIdx.x;
    for (int i = t; i < Nst; i += 256) bs[i] = b[i];
    __syncthreads();
    int idx = blockIdx.x * 256 + t;
    int j = idx >> 9;            // 0..7 -> power A^(j+1)
    int n = idx & 511;
    const float* row = g_pw[j] + (long)n * Nst;
    float s = 0.f;
#pragma unroll 8
    for (int k = 0; k < Nst; k++) s += row[k] * bs[k];
    g_G[(long)(j + 1) * Nst + n] = s;
}

__global__ void rev_k() {
    int idx = blockIdx.x * 256 + threadIdx.x;   // float4 index, total Tc*Nst/4
    int n4 = idx & 127;
    int i  = idx >> 7;
    *(float4*)&g_Grev[(long)i * Nst + n4 * 4] =
        *(const float4*)&g_G[(long)(Tc - 1 - i) * Nst + n4 * 4];
}

__global__ void gmat_k() {
    long idx = (long)blockIdx.x * 256 + threadIdx.x;  // float4 index
    int n4 = (int)(idx & 127);
    long r = idx >> 7;
    int j = (int)(r & (Tc - 1));
    int i = (int)(r >> 7);
    float4 v = make_float4(0.f, 0.f, 0.f, 0.f);
    if (j >= i) v = *(const float4*)&g_G[(long)(j - i) * Nst + n4 * 4];
    *(float4*)&g_Gmat[(long)i * TN + (long)j * Nst + n4 * 4] = v;
}

static void gemm(const float* A, const float* B, float* C, const float* Dp,
                 int M, int Nn, int K,
                 long aBase, int aBRK, long aBS, long aRS, long aZS,
                 long bLd, int bTrans, long bZS,
                 long cBase, int cBRK, long cBS, long cRS, long cZS,
                 long dBase, int nz)
{
    dim3 grid(Nn / 128, (M + 63) / 64, nz);
    gemm_k<<<grid, 256>>>(A, B, C, Dp, M, K,
                          aBase, aBRK, aBS, aRS, aZS,
                          bLd, bTrans, bZS,
                          cBase, cBRK, cBS, cRS, cZS, dBase);
}

extern "C" void kernel_launch(void* const* d_in, const int* in_sizes, int n_in,
                              void* d_out, int out_size)
{
    const float* u  = (const float*)d_in[0];   // (L,)
    const float* Ab = (const float*)d_in[1];   // (N,N)
    const float* Bb = (const float*)d_in[2];   // (N,1)
    const float* x0 = (const float*)d_in[3];   // (N,)
    float* out = (float*)d_out;                // (L,N)

    float *pw, *G, *Grev, *Gmat, *R0, *R1;
    cudaGetSymbolAddress((void**)&pw,   g_pw);
    cudaGetSymbolAddress((void**)&G,    g_G);
    cudaGetSymbolAddress((void**)&Grev, g_Grev);
    cudaGetSymbolAddress((void**)&Gmat, g_Gmat);
    cudaGetSymbolAddress((void**)&R0,   g_R0);
    cudaGetSymbolAddress((void**)&R1,   g_R1);

    auto PW = [&](int s) { return pw + (long)s * NN; };

    // ---- Powers: A^1..A^8 in 3 launches (z-batched), then 12 serial squarings
    cudaMemcpyAsync(PW(0), Ab, NN * sizeof(float), cudaMemcpyDeviceToDevice);
    // A^2 = A @ A
    gemm(PW(0), PW(0), PW(1), nullptr, Nst, Nst, Nst,
         0, 1, Nst, 0, 0,   Nst, 0, 0,   0, 1, Nst, 0, 0,  0, 1);
    // [A^3, A^4] = [A^1, A^2] @ A^2
    gemm(PW(0), PW(1), PW(2), nullptr, Nst, Nst, Nst,
         0, 1, Nst, 0, NN,  Nst, 0, 0,   0, 1, Nst, 0, NN, 0, 2);
    // [A^5..A^8] = [A^1..A^4] @ A^4
    gemm(PW(0), PW(3), PW(4), nullptr, Nst, Nst, Nst,
         0, 1, Nst, 0, NN,  Nst, 0, 0,   0, 1, Nst, 0, NN, 0, 4);
    // A^16, A^32, A^64, A^128, ..., A^32768
    for (int s = 8; s <= 19; s++) {
        const float* X = (s == 8) ? PW(7) : PW(s - 1);
        gemm(X, X, PW(s), nullptr, Nst, Nst, Nst,
             0, 1, Nst, 0, 0,  Nst, 0, 0,  0, 1, Nst, 0, 0, 0, 1);
    }

    // ---- Conv kernel G[0..127]: row 0 = b; rows 1..8 parallel matvecs; doublings
    cudaMemcpyAsync(G, Bb, Nst * sizeof(float), cudaMemcpyDeviceToDevice);
    gvec_k<<<16, 256>>>(Bb);
    for (int t = 3; t <= 6; t++) {          // s = 8,16,32,64 ; powers PW(7..10)
        int s = 1 << t;
        gemm(G, PW(4 + t), G + (long)s * Nst, nullptr, s, Nst, Nst,
             0, 1, Nst, 0, 0,  Nst, 1, 0,  0, 1, Nst, 0, 0, 0, 1);
    }
    rev_k<<<(Tc * Nst / 4) / 256, 256>>>();

    // ---- Driving terms d[c]
    cudaMemcpyAsync(R0, x0, Nst * sizeof(float), cudaMemcpyDeviceToDevice);
    gemm(u, Grev, R0 + Nst, nullptr, Cc - 1, Nst, Tc,
         0, 1, Tc, 0, 0,  Nst, 0, 0,  0, 1, Nst, 0, 0, 0, 1);

    // ---- Log-doubling scan over chunk states (9 levels, copy only h rows)
    float* cur = R0; float* nxt = R1;
    for (int k = 0; k < 9; k++) {
        int h = 1 << k;
        cudaMemcpyAsync(nxt, cur, (size_t)h * Nst * sizeof(float),
                        cudaMemcpyDeviceToDevice);
        // nxt[h:] = cur[:C-h] @ (A^(128*2^k))^T + cur[h:]
        gemm(cur, PW(11 + k), nxt + (long)h * Nst, cur, Cc - h, Nst, Nst,
             0, 1, Nst, 0, 0,  Nst, 1, 0,  0, 1, Nst, 0, 0,
             (long)h * Nst, 1);
        float* tmp = cur; cur = nxt; nxt = tmp;
    }
    float* St = cur;   // St[c] = state entering chunk c

    // ---- Part A stage 1: rows j=0..7 of every chunk in ONE batched GEMM (z=8)
    // out[c*T + j] = St[c] @ (A^(j+1))^T
    gemm(St, PW(0), out, nullptr, Cc, Nst, Nst,
         0, 1, Nst, 0, 0,          // A: same for all z
         Nst, 1, NN,               // B: A^(z+1), transposed
         0, 1, (long)TN, 0, (long)Nst,  // C: chunk stride TN; z shifts row j
         0, 8);

    // ---- Part A stage 2: log-doubling over row blocks (4 steps, huge M)
    // rows [R, 2R) = rows [0, R) @ (A^R)^T ; R = 8,16,32,64
    const int pwIdx[4] = {7, 8, 9, 10};     // A^8, A^16, A^32, A^64
    for (int s = 0; s < 4; s++) {
        int R = 8 << s;
        gemm(out, PW(pwIdx[s]), out, nullptr, Cc * R, Nst, Nst,
             0, R, (long)TN, (long)Nst, 0,
             Nst, 1, 0,
             (long)R * Nst, R, (long)TN, (long)Nst, 0,
             0, 1);
    }

    // ---- Part B: within-chunk causal conv, accumulated into out
    gmat_k<<<(long)Tc * TN / 4 / 256, 256>>>();
    gemm(u, Gmat, out, out, Cc, TN, Tc,
         0, 1, Tc, 0, 0,  (long)TN, 0, 0,  0, 1, (long)TN, 0, 0,
         0, 1);

    (void)in_sizes; (void)n_in; (void)out_size;
}

// round 12
// speedup vs baseline: 3.2493x; 1.4613x over previous
#include <cuda_runtime.h>
#include <cuda_bf16.h>
#include <cstdint>

#define Nst 512
#define Cc  512
#define NN  ((long)Nst * Nst)
#define KS3 1536
#define SLOTE ((long)Nst * KS3)
#define KC   64
#define LDA  72                          // KC + 8 bf16 pad (16B-aligned rows)
#define SMEM_HALF (128 * LDA)            // bf16 elems, one matrix one stage
#define SMEM_DYN  (4 * SMEM_HALF * 2)    // bytes: A+B, double buffered = 73728

typedef __nv_bfloat16 bf16;

// ---------------- static scratch (no runtime allocation) ----------------
__device__ float g_pw[20][Nst * Nst];        // fp32 powers
__device__ bf16  g_pwA[20][Nst * KS3];       // A-form split [h|l|h], natural rows
__device__ bf16  g_pwB[20][Nst * KS3];       // B-form split [h|h|l], TRANSPOSED (for squaring)
__device__ bf16  g_pwN[20][Nst * KS3];       // B-form split [h|h|l], natural rows (for x@P^T)
__device__ float g_G[128 * Nst];             // G[m] = A^m b
__device__ bf16  g_GA[64 * KS3];             // A-form split of G rows 0..63
__device__ bf16  g_GrevB[Nst * 384];         // B-form of reversed G (K=128)
__device__ bf16  g_UA[Cc * 384];             // A-form of u chunks (K=128)
__device__ bf16  g_GmatB[(size_t)65536 * 384];
__device__ float g_R0[Cc * Nst], g_R1[Cc * Nst];
__device__ bf16  g_R0e[Cc * KS3], g_R1e[Cc * KS3];
__device__ float g_OutA[(size_t)128 * Cc * Nst];   // [j][c][n]
__device__ bf16  g_OutAe[(size_t)64 * Cc * KS3];   // A-form of rows j=0..63

// ---------------- helpers ----------------
__device__ __forceinline__ uint32_t s2u(const void* p) {
    uint32_t a;
    asm("{ .reg .u64 t; cvta.to.shared.u64 t, %1; cvt.u32.u64 %0, t; }" : "=r"(a) : "l"(p));
    return a;
}
__device__ __forceinline__ void cpasync(uint32_t d, const void* g, int srcsz) {
    asm volatile("cp.async.ca.shared.global [%0], [%1], 16, %2;"
                 :: "r"(d), "l"(g), "r"(srcsz) : "memory");
}
__device__ __forceinline__ void cpcommit() {
    asm volatile("cp.async.commit_group;" ::: "memory");
}
template<int n> __device__ __forceinline__ void cpwait() {
    asm volatile("cp.async.wait_group %0;" :: "n"(n) : "memory");
}
__device__ __forceinline__ void ldsm4(uint32_t &r0, uint32_t &r1, uint32_t &r2, uint32_t &r3, uint32_t a) {
    asm volatile("ldmatrix.sync.aligned.m8n8.x4.shared.b16 {%0,%1,%2,%3}, [%4];"
                 : "=r"(r0), "=r"(r1), "=r"(r2), "=r"(r3) : "r"(a));
}
__device__ __forceinline__ void mma16816(float* c, const uint32_t* a, const uint32_t* b) {
    asm volatile("mma.sync.aligned.m16n8k16.row.col.f32.bf16.bf16.f32 "
                 "{%0,%1,%2,%3}, {%4,%5,%6,%7}, {%8,%9}, {%0,%1,%2,%3};"
                 : "+f"(c[0]), "+f"(c[1]), "+f"(c[2]), "+f"(c[3])
                 : "r"(a[0]), "r"(a[1]), "r"(a[2]), "r"(a[3]), "r"(b[0]), "r"(b[1]));
}

// ============================================================================
// bf16 tensor-core GEMM: C[m,g] = sum_k A[m,k]*B[g,k]  (+Dadd), M-guarded.
// CTA tile 128x128, 8 warps (4m x 2n), warp tile 32x64, KC=64 double-buffered.
// Optional epilogue emissions: SA = A-form split of C rows (Nn must be 512);
// SB = B-form TRANSPOSED split of C (for the next squaring).
// dMode: 0 none, 1 row-major add (dBase,dRS), 2 OutA-layout add for Part B.
// ============================================================================
__global__ void __launch_bounds__(256, 2)
tgemm_k(const bf16* __restrict__ A, long aBase, long aZS,
        const bf16* __restrict__ B, long bBase, long bZS,
        float* __restrict__ C, long cBase, long cRS, long cZS,
        const float* __restrict__ Dadd, long dBase, long dRS, int dMode,
        bf16* __restrict__ SA, long saBase, long saZS,
        bf16* __restrict__ SB, long sbBase, long sbZS,
        int M, int Ks)
{
    extern __shared__ bf16 sm[];
    bf16* AsBuf = sm;                     // [2][128][LDA]
    bf16* BsBuf = sm + 2 * SMEM_HALF;

    int tid = threadIdx.x;
    int lane = tid & 31, wid = tid >> 5;
    int bm = blockIdx.y << 7, bn = blockIdx.x << 7;
    int z = blockIdx.z;
    const bf16* Ap = A + aBase + (long)z * aZS;
    const bf16* Bp = B + bBase + (long)z * bZS;
    int wm = (wid & 3) << 5;      // warp m offset (0..96)
    int wn = (wid >> 2) << 6;     // warp n offset (0 or 64)

    float acc[2][8][4];
#pragma unroll
    for (int i = 0; i < 2; i++)
#pragma unroll
        for (int j = 0; j < 8; j++)
#pragma unroll
            for (int p = 0; p < 4; p++) acc[i][j][p] = 0.f;

    int nc = Ks / KC;

    auto ldg = [&](int s) {
        int kc = s * KC;
        bf16* as = AsBuf + (s & 1) * SMEM_HALF;
        bf16* bs = BsBuf + (s & 1) * SMEM_HALF;
#pragma unroll
        for (int t = 0; t < 4; t++) {
            int id = tid + t * 256;
            int r = id >> 3, c = (id & 7) << 3;     // 8 bf16 per 16B chunk
            int gr = bm + r;
            int grs = gr < M ? gr : 0;
            cpasync(s2u(as + r * LDA + c), Ap + (long)grs * Ks + kc + c, gr < M ? 16 : 0);
            cpasync(s2u(bs + r * LDA + c), Bp + (long)(bn + r) * Ks + kc + c, 16);
        }
    };

    auto comp = [&](int s) {
        const bf16* as = AsBuf + (s & 1) * SMEM_HALF;
        const bf16* bs = BsBuf + (s & 1) * SMEM_HALF;
        int lr = lane & 15, lk = (lane >> 4) << 3;
#pragma unroll
        for (int ks = 0; ks < KC / 16; ks++) {
            uint32_t af[2][4], bfr[8][2];
#pragma unroll
            for (int mi = 0; mi < 2; mi++) {
                uint32_t a = s2u(as + (wm + mi * 16 + lr) * LDA + ks * 16 + lk);
                ldsm4(af[mi][0], af[mi][1], af[mi][2], af[mi][3], a);
            }
#pragma unroll
            for (int nj = 0; nj < 4; nj++) {
                uint32_t r0, r1, r2, r3;
                uint32_t a = s2u(bs + (wn + nj * 16 + lr) * LDA + ks * 16 + lk);
                ldsm4(r0, r1, r2, r3, a);
                bfr[nj * 2][0] = r0;     bfr[nj * 2][1] = r2;
                bfr[nj * 2 + 1][0] = r1; bfr[nj * 2 + 1][1] = r3;
            }
#pragma unroll
            for (int mi = 0; mi < 2; mi++)
#pragma unroll
                for (int ni = 0; ni < 8; ni++)
                    mma16816(acc[mi][ni], af[mi], bfr[ni]);
        }
    };

    ldg(0); cpcommit();
    for (int s = 0; s < nc; s++) {
        if (s + 1 < nc) { ldg(s + 1); cpcommit(); cpwait<1>(); }
        else cpwait<0>();
        __syncthreads();
        comp(s);
        __syncthreads();
    }

    // ---- epilogue ----
    int group = lane >> 2, t4 = lane & 3;
#pragma unroll
    for (int mi = 0; mi < 2; mi++) {
#pragma unroll
        for (int rh = 0; rh < 2; rh++) {
            int m = bm + wm + mi * 16 + rh * 8 + group;
            if (m >= M) continue;
            long cro = cBase + (long)z * cZS + (long)m * cRS;
#pragma unroll
            for (int ni = 0; ni < 8; ni++) {
                int n = bn + wn + ni * 8 + t4 * 2;
                float v0 = acc[mi][ni][rh * 2 + 0];
                float v1 = acc[mi][ni][rh * 2 + 1];
                if (dMode == 1) {
                    const float* dp = Dadd + dBase + (long)m * dRS + n;
                    v0 += dp[0]; v1 += dp[1];
                } else if (dMode == 2) {
                    long db = ((long)(n >> 9) << 18) + ((long)m << 9) + (n & 511);
                    v0 += Dadd[db]; v1 += Dadd[db + 1];
                }
                C[cro + n] = v0; C[cro + n + 1] = v1;
                if (SA) {
                    bf16 h0 = __float2bfloat16(v0);
                    bf16 l0 = __float2bfloat16(v0 - __bfloat162float(h0));
                    bf16 h1 = __float2bfloat16(v1);
                    bf16 l1 = __float2bfloat16(v1 - __bfloat162float(h1));
                    long so = saBase + (long)z * saZS + (long)m * KS3 + n;
                    SA[so] = h0;      SA[so + 512] = l0;  SA[so + 1024] = h0;
                    SA[so + 1] = h1;  SA[so + 513] = l1;  SA[so + 1025] = h1;
                }
                if (SB) {
                    bf16 h0 = __float2bfloat16(v0);
                    bf16 l0 = __float2bfloat16(v0 - __bfloat162float(h0));
                    bf16 h1 = __float2bfloat16(v1);
                    bf16 l1 = __float2bfloat16(v1 - __bfloat162float(h1));
                    long so0 = sbBase + (long)z * sbZS + (long)n * KS3 + m;
                    SB[so0] = h0; SB[so0 + 512] = h0; SB[so0 + 1024] = l0;
                    long so1 = so0 + KS3;
                    SB[so1] = h1; SB[so1 + 512] = h1; SB[so1 + 1024] = l1;
                }
            }
        }
    }
}

// ---------------- conversion kernels ----------------
__global__ void splitA_k(const float* __restrict__ src, int ld,
                         bf16* __restrict__ dst, int M, int K) {
    long idx = (long)blockIdx.x * 256 + threadIdx.x;
    if (idx >= (long)M * K) return;
    int mm = (int)(idx / K), k = (int)(idx - (long)mm * K);
    float v = src[(long)mm * ld + k];
    bf16 h = __float2bfloat16(v);
    bf16 l = __float2bfloat16(v - __bfloat162float(h));
    long o = (long)mm * 3 * K + k;
    dst[o] = h; dst[o + K] = l; dst[o + 2 * K] = h;
}
__global__ void splitBT_k(const float* __restrict__ src, bf16* __restrict__ dst) {
    int idx = blockIdx.x * 256 + threadIdx.x;    // 512*512
    int n = idx >> 9, k = idx & 511;
    float v = src[(long)k * Nst + n];
    bf16 h = __float2bfloat16(v);
    bf16 l = __float2bfloat16(v - __bfloat162float(h));
    long o = (long)n * KS3 + k;
    dst[o] = h; dst[o + 512] = h; dst[o + 1024] = l;
}
__global__ void splitN_k() {                     // all 20 natural B-form splits
    long idx = (long)blockIdx.x * 256 + threadIdx.x;   // 20*512*512
    int slot = (int)(idx >> 18);
    int rem  = (int)(idx & 262143);
    int n = rem >> 9, k = rem & 511;
    float v = g_pw[slot][n * 512 + k];
    bf16 h = __float2bfloat16(v);
    bf16 l = __float2bfloat16(v - __bfloat162float(h));
    bf16* d = g_pwN[slot] + (long)n * KS3 + k;
    d[0] = h; d[512] = h; d[1024] = l;
}
__global__ void bGrev_k() {
    int idx = blockIdx.x * 256 + threadIdx.x;    // 512*128
    int n = idx >> 7, i = idx & 127;
    float v = g_G[(long)(127 - i) * Nst + n];
    bf16 h = __float2bfloat16(v);
    bf16 l = __float2bfloat16(v - __bfloat162float(h));
    long o = (long)n * 384 + i;
    g_GrevB[o] = h; g_GrevB[o + 128] = h; g_GrevB[o + 256] = l;
}
__global__ void gmatB_k() {
    long idx = (long)blockIdx.x * 256 + threadIdx.x;  // 65536*128
    int i = (int)(idx & 127);
    long rr = idx >> 7;                               // g = j*512+n
    int j = (int)(rr >> 9), n = (int)(rr & 511);
    float v = (j >= i) ? g_G[(long)(j - i) * Nst + n] : 0.f;
    bf16 h = __float2bfloat16(v);
    bf16 l = __float2bfloat16(v - __bfloat162float(h));
    long o = rr * 384 + i;
    g_GmatB[o] = h; g_GmatB[o + 128] = h; g_GmatB[o + 256] = l;
}
__global__ void gvec_k(const float* __restrict__ b) {
    __shared__ float bs[Nst];
    int t = threadIdx.x;
    for (int i = t; i < Nst; i += 256) bs[i] = b[i];
    __syncthreads();
    int idx = blockIdx.x * 256 + t;
    int j = idx >> 9, n = idx & 511;
    const float* row = g_pw[j] + (long)n * Nst;
    float s = 0.f;
#pragma unroll 8
    for (int k = 0; k < Nst; k++) s += row[k] * bs[k];
    g_G[(long)(j + 1) * Nst + n] = s;
}

// ---------------- host ----------------
static void TG(const bf16* A, long aB, long aZ,
               const bf16* Bp, long bB, long bZ,
               float* Cp, long cB, long cRS, long cZ,
               const float* Dp, long dB, long dRS, int dM,
               bf16* SAp, long saB, long saZ,
               bf16* SBp, long sbB, long sbZ,
               int M, int Nn, int Ks, int nz)
{
    dim3 g(Nn / 128, (M + 127) / 128, nz);
    tgemm_k<<<g, 256, SMEM_DYN>>>(A, aB, aZ, Bp, bB, bZ, Cp, cB, cRS, cZ,
                                  Dp, dB, dRS, dM, SAp, saB, saZ, SBp, sbB, sbZ,
                                  M, Ks);
}

extern "C" void kernel_launch(void* const* d_in, const int* in_sizes, int n_in,
                              void* d_out, int out_size)
{
    const float* u  = (const float*)d_in[0];
    const float* Ab = (const float*)d_in[1];
    const float* Bb = (const float*)d_in[2];
    const float* x0 = (const float*)d_in[3];
    float* out = (float*)d_out;

    cudaFuncSetAttribute(tgemm_k, cudaFuncAttributeMaxDynamicSharedMemorySize, SMEM_DYN);

    float *pw, *G, *R0, *R1, *OutA;
    bf16 *pwA, *pwB, *pwN, *GA, *GrevB, *UA, *GmatB, *R0e, *R1e, *OutAe;
    cudaGetSymbolAddress((void**)&pw,    g_pw);
    cudaGetSymbolAddress((void**)&pwA,   g_pwA);
    cudaGetSymbolAddress((void**)&pwB,   g_pwB);
    cudaGetSymbolAddress((void**)&pwN,   g_pwN);
    cudaGetSymbolAddress((void**)&G,     g_G);
    cudaGetSymbolAddress((void**)&GA,    g_GA);
    cudaGetSymbolAddress((void**)&GrevB, g_GrevB);
    cudaGetSymbolAddress((void**)&UA,    g_UA);
    cudaGetSymbolAddress((void**)&GmatB, g_GmatB);
    cudaGetSymbolAddress((void**)&R0,    g_R0);
    cudaGetSymbolAddress((void**)&R1,    g_R1);
    cudaGetSymbolAddress((void**)&R0e,   g_R0e);
    cudaGetSymbolAddress((void**)&R1e,   g_R1e);
    cudaGetSymbolAddress((void**)&OutA,  g_OutA);
    cudaGetSymbolAddress((void**)&OutAe, g_OutAe);

    auto PWf = [&](int s) { return pw  + (long)s * NN; };
    auto PA  = [&](int s) { return pwA + (long)s * SLOTE; };
    auto PB  = [&](int s) { return pwB + (long)s * SLOTE; };
    auto PN  = [&](int s) { return pwN + (long)s * SLOTE; };

    // ---- input splits ----
    splitA_k<<<(512 * 512) / 256, 256>>>(Ab, 512, PA(0), 512, 512);
    splitBT_k<<<(512 * 512) / 256, 256>>>(Ab, PB(0));
    cudaMemcpyAsync(PWf(0), Ab, NN * sizeof(float), cudaMemcpyDeviceToDevice);
    splitA_k<<<(512 * 128) / 256, 256>>>(u, 128, UA, 512, 128);
    splitA_k<<<2, 256>>>(x0, 512, R0e, 1, 512);
    cudaMemcpyAsync(R0, x0, Nst * sizeof(float), cudaMemcpyDeviceToDevice);

    // ---- power chain: slots 0..7 = A^1..A^8; 8..10 = A^16/32/64; 11..19 = A^(128*2^k)
    TG(PA(0), 0, 0, PB(0), 0, 0, PWf(1), 0, 512, 0,
       nullptr, 0, 0, 0, PA(1), 0, 0, PB(1), 0, 0, 512, 512, KS3, 1);          // A^2
    TG(PA(0), 0, SLOTE, PB(1), 0, 0, PWf(2), 0, 512, NN,
       nullptr, 0, 0, 0, PA(2), 0, SLOTE, PB(2), 0, SLOTE, 512, 512, KS3, 2);  // A^3,A^4
    TG(PA(0), 0, SLOTE, PB(3), 0, 0, PWf(4), 0, 512, NN,
       nullptr, 0, 0, 0, PA(4), 0, SLOTE, PB(4), 0, SLOTE, 512, 512, KS3, 4);  // A^5..A^8
    for (int s = 8; s <= 19; s++)
        TG(PA(s - 1), 0, 0, PB(s - 1), 0, 0, PWf(s), 0, 512, 0,
           nullptr, 0, 0, 0, PA(s), 0, 0, PB(s), 0, 0, 512, 512, KS3, 1);

    // natural B-form splits of all powers (needed for every x @ P^T GEMM below)
    splitN_k<<<20480, 256>>>();

    // ---- conv kernel G[0..127] ----
    cudaMemcpyAsync(G, Bb, Nst * sizeof(float), cudaMemcpyDeviceToDevice);
    gvec_k<<<16, 256>>>(Bb);                                   // G[1..8] fp32 matvecs
    splitA_k<<<(8 * 512) / 256, 256>>>(G, 512, GA, 8, 512);
    for (int t = 3; t <= 6; t++) {
        int sI = 1 << t;                                       // 8,16,32,64
        TG(GA, 0, 0, PN(4 + t), 0, 0, G, (long)sI * 512, 512, 0,
           nullptr, 0, 0, 0,
           (t < 6) ? GA : nullptr, (long)sI * KS3, 0, nullptr, 0, 0,
           sI, 512, KS3, 1);
    }
    bGrev_k<<<(512 * 128) / 256, 256>>>();
    gmatB_k<<<32768, 256>>>();

    // ---- driving terms rows 1..511 ----
    TG(UA, 0, 0, GrevB, 0, 0, R0, 512, 512, 0,
       nullptr, 0, 0, 0, R0e, KS3, 0, nullptr, 0, 0, 511, 512, 384, 1);

    // ---- log-doubling scan (9 levels) ----
    float* cur = R0;  float* nxt = R1;
    bf16*  curE = R0e; bf16* nxtE = R1e;
    for (int k = 0; k < 9; k++) {
        int h = 1 << k;
        cudaMemcpyAsync(nxt, cur, (size_t)h * Nst * sizeof(float),
                        cudaMemcpyDeviceToDevice);
        cudaMemcpyAsync(nxtE, curE, (size_t)h * KS3 * sizeof(bf16),
                        cudaMemcpyDeviceToDevice);
        TG(curE, 0, 0, PN(11 + k), 0, 0, nxt, (long)h * 512, 512, 0,
           cur, (long)h * 512, 512, 1,
           nxtE, (long)h * KS3, 0, nullptr, 0, 0,
           512 - h, 512, KS3, 1);
        float* tf = cur; cur = nxt; nxt = tf;
        bf16*  tb = curE; curE = nxtE; nxtE = tb;
    }

    // ---- Part A stage 1: rows j=0..7 via one z=8 batched GEMM ----
    TG(curE, 0, 0, pwN, 0, SLOTE, OutA, 0, 512, (long)Cc * 512,
       nullptr, 0, 0, 0, OutAe, 0, (long)Cc * KS3, nullptr, 0, 0,
       512, 512, KS3, 8);

    // ---- Part A stage 2: log-doubling over j-blocks (R=8,16,32,64) ----
    for (int s = 0; s < 4; s++) {
        int R = 8 << s;                       // B = A^R -> slots 7,8,9,10
        TG(OutAe, 0, 0, PN(7 + s), 0, 0, OutA, (long)R * Cc * 512, 512, 0,
           nullptr, 0, 0, 0,
           (s < 3) ? OutAe : nullptr, (long)R * Cc * KS3, 0, nullptr, 0, 0,
           R * Cc, 512, KS3, 1);
    }

    // ---- Part B: causal conv + Part A combine, directly into d_out ----
    TG(UA, 0, 0, GmatB, 0, 0, out, 0, 65536, 0,
       OutA, 0, 0, 2,
       nullptr, 0, 0, nullptr, 0, 0,
       512, 65536, 384, 1);

    (void)in_sizes; (void)n_in; (void)out_size;
}